// round 7
// baseline (speedup 1.0000x reference)
#include <cuda_runtime.h>
#include <math.h>

// Problem constants (fixed by the dataset)
#define SD 5
#define OD 32
#define NB 256
#define TT 8192

// ---------------- scratch (device globals; allocation-free) ----------------
// proj layout: [(t*6+k)*NB + b], k=0..4 -> (C^T R^-1 y)_k, k=5 -> y^T R^-1 y
__device__ float  g_proj[TT * 6 * NB];     // 50.3 MB
// J layout: [t*26 + e], e<25 = P_post (row-major), e=25 = logdet S_t
__device__ float  g_J[TT * 26];
__device__ float  g_U[25];                 // U = C^T R^-1 C
__device__ double g_llpart[NB * 256];      // [b][chunk] partial ll (b-major)

// ---------------- Riccati config (merged into kernel 1, blocks 0..3) -------
#define R_LR 8
#define R_WR 24
#define R_NBLK 4                    // 4 blocks * 256 threads = 1024 chunks

// ---------------- projection config ----------------
#define P_TT 2                      // time steps per proj block
#define P_NBLK (TT / P_TT)          // 4096
#define P_SMEM (P_TT * NB * 33 * 4) // 67584 B

// ---------------- z-recursion + covs-broadcast config ----------------
#define Z_L 32
#define Z_W 48
#define Z_NCHUNK (TT / Z_L)         // 256
#define Z_MAXSTEPS (Z_L + Z_W)      // 80
#define BC_TILE 32
#define BC_NBLK (TT / BC_TILE)      // 256
#define ZB_SMEM (Z_MAXSTEPS * 26 * 4 + NB * 41 * 4)   // 50304 B

// output offsets (tuple flattened: states, covs, ll)
#define OUT_STATES 0
#define OUT_COVS   ((size_t)NB * TT * SD)
#define OUT_LL     (OUT_COVS + (size_t)NB * TT * SD * SD)

// ============================================================================
// Kernel 1: fused  (a) Riccati recursion -> g_J, g_U      [blocks 0..3]
//                  (b) observation projection y -> g_proj [blocks 4..4099]
// Riccati is tiny (1024 serial chains); proj saturates HBM meanwhile.
// ============================================================================
__global__ __launch_bounds__(256, 3) void k_rp(
    const float* __restrict__ y,
    const float* __restrict__ Ain,
    const float* __restrict__ Cin,
    const float* __restrict__ Qlog,
    const float* __restrict__ Rlog)
{
    extern __shared__ float sm[];
    const int tid = threadIdx.x;

    if (blockIdx.x < R_NBLK) {
        // ---------------- Riccati chains ----------------
        const int chunk = blockIdx.x * 256 + tid;

        float a[25];
        #pragma unroll
        for (int i = 0; i < 25; i++) a[i] = Ain[i];
        float q[5];
        #pragma unroll
        for (int k = 0; k < 5; k++) q[k] = expf(Qlog[k]);

        float U[25];
        #pragma unroll
        for (int i = 0; i < 25; i++) U[i] = 0.f;
        float logdetR = 0.f;
        for (int o = 0; o < OD; o++) {
            float rl = Rlog[o];
            logdetR += rl;
            float ri = expf(-rl);
            float cv[5];
            #pragma unroll
            for (int k = 0; k < 5; k++) cv[k] = Cin[o * 5 + k];
            #pragma unroll
            for (int i = 0; i < 5; i++) {
                float f = ri * cv[i];
                #pragma unroll
                for (int j = 0; j < 5; j++) U[i * 5 + j] += f * cv[j];
            }
        }
        if (chunk == 0) {
            #pragma unroll
            for (int i = 0; i < 25; i++) g_U[i] = U[i];
        }

        const int town = chunk * R_LR;
        const int tend = town + R_LR;
        int t0s = town - R_WR; if (t0s < 0) t0s = 0;

        float P[25];
        #pragma unroll
        for (int i = 0; i < 25; i++) P[i] = (i % 6 == 0) ? 1.f : 0.f;

        for (int t = t0s; t < tend; ++t) {
            float Tm[25], Pp[25];
            #pragma unroll
            for (int i = 0; i < 5; i++)
                #pragma unroll
                for (int j = 0; j < 5; j++) {
                    float s = 0.f;
                    #pragma unroll
                    for (int k = 0; k < 5; k++) s += a[i * 5 + k] * P[k * 5 + j];
                    Tm[i * 5 + j] = s;
                }
            #pragma unroll
            for (int i = 0; i < 5; i++)
                #pragma unroll
                for (int j = 0; j < 5; j++) {
                    float s = 0.f;
                    #pragma unroll
                    for (int k = 0; k < 5; k++) s += Tm[i * 5 + k] * a[j * 5 + k];
                    Pp[i * 5 + j] = s;
                }
            #pragma unroll
            for (int i = 0; i < 5; i++) Pp[i * 5 + i] += q[i];

            float M[25], V[25];
            #pragma unroll
            for (int i = 0; i < 5; i++)
                #pragma unroll
                for (int j = 0; j < 5; j++) {
                    float s = (i == j) ? 1.f : 0.f;
                    #pragma unroll
                    for (int k = 0; k < 5; k++) s += U[i * 5 + k] * Pp[k * 5 + j];
                    M[i * 5 + j] = s;
                }
            #pragma unroll
            for (int i = 0; i < 25; i++) V[i] = (i % 6 == 0) ? 1.f : 0.f;
            float det = 1.f;
            #pragma unroll
            for (int k = 0; k < 5; k++) {
                float piv = M[k * 5 + k];
                det *= piv;
                float ip = 1.f / piv;
                #pragma unroll
                for (int j = 0; j < 5; j++) { M[k * 5 + j] *= ip; V[k * 5 + j] *= ip; }
                #pragma unroll
                for (int i2 = 0; i2 < 5; i2++) {
                    if (i2 == k) continue;
                    float f = M[i2 * 5 + k];
                    #pragma unroll
                    for (int j = 0; j < 5; j++) {
                        M[i2 * 5 + j] -= f * M[k * 5 + j];
                        V[i2 * 5 + j] -= f * V[k * 5 + j];
                    }
                }
            }
            #pragma unroll
            for (int i = 0; i < 5; i++)
                #pragma unroll
                for (int j = 0; j < 5; j++) {
                    float s = 0.f;
                    #pragma unroll
                    for (int k = 0; k < 5; k++) s += Pp[i * 5 + k] * V[k * 5 + j];
                    P[i * 5 + j] = s;
                }

            if (t >= town) {
                float ld = logdetR + logf(det);
                #pragma unroll
                for (int e = 0; e < 25; e++) g_J[t * 26 + e] = P[e];
                g_J[t * 26 + 25] = ld;
            }
        }
    } else {
        // ---------------- projection: 2 time steps x all 256 batches -------
        float* sy = sm;                 // [P_TT][NB][33]
        __shared__ float crv[OD * 5];
        __shared__ float rin[OD];
        const int t0 = (blockIdx.x - R_NBLK) * P_TT;

        if (tid < OD * 5) {
            int o = tid / 5;
            crv[tid] = Cin[tid] * expf(-Rlog[o]);
        } else if (tid < OD * 5 + OD) {
            rin[tid - OD * 5] = expf(-Rlog[tid - OD * 5]);
        }

        const float4* y4 = (const float4*)y;
        #pragma unroll
        for (int it = 0; it < 2 * NB * 8 / 256; ++it) {  // 16 iters
            int f = it * 256 + tid;
            int qq = f & 7;
            int tt = (f >> 3) & (P_TT - 1);
            int b  = f >> 4;
            float4 v = __ldcs(&y4[((size_t)b * TT + t0 + tt) * 8 + qq]);
            float* s = &sy[(tt * NB + b) * 33 + qq * 4];
            s[0] = v.x; s[1] = v.y; s[2] = v.z; s[3] = v.w;
        }
        __syncthreads();

        const int b = tid;
        #pragma unroll
        for (int tt = 0; tt < P_TT; ++tt) {
            const float* row = &sy[(tt * NB + b) * 33];
            float c0 = 0, c1 = 0, c2 = 0, c3 = 0, c4 = 0, syy = 0;
            #pragma unroll
            for (int o = 0; o < OD; o++) {
                float yv = row[o];
                syy += (yv * rin[o]) * yv;
                c0 += crv[o * 5 + 0] * yv;
                c1 += crv[o * 5 + 1] * yv;
                c2 += crv[o * 5 + 2] * yv;
                c3 += crv[o * 5 + 3] * yv;
                c4 += crv[o * 5 + 4] * yv;
            }
            float* pd = &g_proj[((size_t)(t0 + tt) * 6) * NB + b];
            pd[0 * NB] = c0; pd[1 * NB] = c1; pd[2 * NB] = c2;
            pd[3 * NB] = c3; pd[4 * NB] = c4; pd[5 * NB] = syy;
        }
    }
}

// ---------------- one z step ----------------
#define Z_STEP(CCBUF, U_)                                                     \
    {                                                                         \
        float zp[5];                                                          \
        _Pragma("unroll")                                                     \
        for (int i = 0; i < 5; i++)                                           \
            zp[i] = a[i*5+0]*z0 + a[i*5+1]*z1 + a[i*5+2]*z2                   \
                  + a[i*5+3]*z3 + a[i*5+4]*z4;                                \
        float g[5];                                                           \
        _Pragma("unroll")                                                     \
        for (int i = 0; i < 5; i++) {                                         \
            float sa = 0.f;                                                   \
            _Pragma("unroll")                                                 \
            for (int j = 0; j < 5; j++) sa += U_[i*5+j] * zp[j];              \
            g[i] = sa;                                                        \
        }                                                                     \
        float w[5];                                                           \
        _Pragma("unroll")                                                     \
        for (int i = 0; i < 5; i++) w[i] = (CCBUF)[i] - g[i];                 \
        const float* Jr = &sJ[s * 26];                                        \
        float h[5];                                                           \
        _Pragma("unroll")                                                     \
        for (int i = 0; i < 5; i++) {                                         \
            float sa = 0.f;                                                   \
            _Pragma("unroll")                                                 \
            for (int j = 0; j < 5; j++) sa += Jr[i*5+j] * w[j];               \
            h[i] = sa;                                                        \
        }                                                                     \
        z0 = zp[0]+h[0]; z1 = zp[1]+h[1]; z2 = zp[2]+h[2];                    \
        z3 = zp[3]+h[3]; z4 = zp[4]+h[4];                                     \
        if (s >= warm) {                                                      \
            float cz = 0, zg = 0, wh = 0;                                     \
            _Pragma("unroll")                                                 \
            for (int i = 0; i < 5; i++) {                                     \
                cz += (CCBUF)[i]*zp[i]; zg += zp[i]*g[i]; wh += w[i]*h[i];    \
            }                                                                 \
            float quad = (CCBUF)[5] - 2.f*cz + zg - wh;                       \
            ll -= 0.5 * ((double)OD * 1.8378770664093453                      \
                         + (double)Jr[25] + (double)quad);                    \
            int sl = (s - warm) & 7;                                          \
            float* sb = &sbuf[b * 41 + sl * 5];                               \
            sb[0]=z0; sb[1]=z1; sb[2]=z2; sb[3]=z3; sb[4]=z4;                 \
        }                                                                     \
    }

// ============================================================================
// Kernel 2: fused  (a) z-recursion + states + ll partials [blocks 0..255]
//                  (b) covariance broadcast J -> covs     [blocks 256..511]
// BC's 210MB streaming write fills the HBM pipe while z-blocks sit on
// latency-bound serial chains — one wave total (512 blocks, 4/SM by smem).
// ============================================================================
__global__ __launch_bounds__(256) void k_zbc(
    const float* __restrict__ Ain, float* __restrict__ out)
{
    extern __shared__ float sm[];
    const int tid = threadIdx.x;

    if (blockIdx.x < Z_NCHUNK) {
        float* sJ   = sm;                         // [Z_MAXSTEPS][26]
        float* sbuf = sm + Z_MAXSTEPS * 26;       // [NB][41]

        const int chunk = blockIdx.x;
        const int town = chunk * Z_L;
        int t0 = town - Z_W; if (t0 < 0) t0 = 0;
        const int nsteps = town + Z_L - t0;       // 32 or 80 (both %8==0)
        const int warm = town - t0;               // 0 or 48

        for (int i = tid; i < nsteps * 26; i += 256) sJ[i] = g_J[t0 * 26 + i];
        __syncthreads();

        float a[25], U[25];
        #pragma unroll
        for (int i = 0; i < 25; i++) { a[i] = Ain[i]; U[i] = g_U[i]; }

        float z0 = 0, z1 = 0, z2 = 0, z3 = 0, z4 = 0;
        double ll = 0.0;
        const int b = tid;
        const float* pbase = &g_proj[(size_t)t0 * 6 * NB + b];

        float bufA[4][6], bufB[4][6];
        #pragma unroll
        for (int u = 0; u < 4; u++)
            #pragma unroll
            for (int k = 0; k < 6; k++)
                bufA[u][k] = pbase[((size_t)u * 6 + k) * NB];

        for (int s8 = 0; s8 < nsteps; s8 += 8) {
            if (s8 + 4 < nsteps) {
                const float* pn = pbase + (size_t)(s8 + 4) * 6 * NB;
                #pragma unroll
                for (int u = 0; u < 4; u++)
                    #pragma unroll
                    for (int k = 0; k < 6; k++)
                        bufB[u][k] = pn[((size_t)u * 6 + k) * NB];
            }
            #pragma unroll
            for (int u = 0; u < 4; u++) {
                const int s = s8 + u;
                Z_STEP(bufA[u], U)
            }
            if (s8 + 8 < nsteps) {
                const float* pn = pbase + (size_t)(s8 + 8) * 6 * NB;
                #pragma unroll
                for (int u = 0; u < 4; u++)
                    #pragma unroll
                    for (int k = 0; k < 6; k++)
                        bufA[u][k] = pn[((size_t)u * 6 + k) * NB];
            }
            #pragma unroll
            for (int u = 0; u < 4; u++) {
                const int s = s8 + 4 + u;
                Z_STEP(bufB[u], U)
            }
            if (s8 >= warm) {
                __syncthreads();
                const int tflush0 = town + (s8 - warm);
                for (int f = tid; f < NB * 40; f += 256) {
                    int bb = f / 40;
                    int u  = f % 40;
                    __stcs(&out[OUT_STATES + ((size_t)bb * TT + tflush0) * 5 + u],
                           sbuf[bb * 41 + u]);
                }
                __syncthreads();
            }
        }
        g_llpart[(size_t)b * Z_NCHUNK + chunk] = ll;
    } else {
        // ---- covariance broadcast: contiguous float4 streaming stores ----
        const int v = blockIdx.x - Z_NCHUNK;       // 0..255
        const int t0 = v * BC_TILE;
        float* sJ = sm;                            // 800 floats
        for (int i = tid; i < BC_TILE * 25; i += 256) {
            int tt = i / 25;
            int e  = i % 25;
            sJ[i] = g_J[(t0 + tt) * 26 + e];
        }
        __syncthreads();
        const float4* sJ4 = (const float4*)sJ;     // 200 float4
        float4* out4 = (float4*)(out + OUT_COVS);
        const unsigned base = (unsigned)v * 200u;
        if (tid < 200) {
            float4 val = sJ4[tid];
            #pragma unroll 4
            for (int bb = 0; bb < NB; ++bb) {
                __stcs(&out4[(size_t)bb * (TT * 25 / 4) + base + tid], val);
            }
        }
    }
}

// ============================================================================
// Kernel 3: ll reduction — block = one batch, 32 lanes, butterfly reduce
// ============================================================================
__global__ __launch_bounds__(32) void k_ll(float* __restrict__ out)
{
    const int b = blockIdx.x;
    const int lane = threadIdx.x;
    const double* p = &g_llpart[(size_t)b * Z_NCHUNK];
    double s = 0.0;
    #pragma unroll
    for (int k = 0; k < Z_NCHUNK / 32; k++) s += p[lane + k * 32];
    #pragma unroll
    for (int d = 16; d >= 1; d >>= 1)
        s += __shfl_xor_sync(0xFFFFFFFFu, s, d);
    if (lane == 0) out[OUT_LL + b] = (float)s;
}

// ============================================================================
extern "C" void kernel_launch(void* const* d_in, const int* in_sizes, int n_in,
                              void* d_out, int out_size)
{
    const float* y  = (const float*)d_in[0];
    const float* A  = (const float*)d_in[1];
    const float* C  = (const float*)d_in[2];
    const float* Ql = (const float*)d_in[3];
    const float* Rl = (const float*)d_in[4];
    float* out = (float*)d_out;

    cudaFuncSetAttribute(k_rp, cudaFuncAttributeMaxDynamicSharedMemorySize, P_SMEM);
    cudaFuncSetAttribute(k_zbc, cudaFuncAttributeMaxDynamicSharedMemorySize, ZB_SMEM);

    k_rp<<<R_NBLK + P_NBLK, 256, P_SMEM>>>(y, A, C, Ql, Rl);
    k_zbc<<<Z_NCHUNK + BC_NBLK, 256, ZB_SMEM>>>(A, out);
    k_ll<<<NB, 32>>>(out);
}

// round 8
// speedup vs baseline: 1.5515x; 1.5515x over previous
#include <cuda_runtime.h>
#include <math.h>
#include <stdint.h>

// Problem constants (fixed by the dataset)
#define SD 5
#define OD 32
#define NB 256
#define TT 8192

// ---------------- scratch (device globals; allocation-free) ----------------
// proj layout: [(t*6+k)*NB + b], k=0..4 -> (C^T R^-1 y)_k, k=5 -> y^T R^-1 y
__device__ float g_proj[TT * 6 * NB];      // 50.3 MB
// J layout: [t*26 + e], e<25 = P_post (row-major), e=25 = logdet S_t
__device__ float g_J[TT * 26];
__device__ float g_U[25];                  // U = C^T R^-1 C
__device__ float g_llpart[NB * 256];       // [b][chunk] partial ll (b-major)

// ---------------- Riccati config ----------------
#define R_LR 8
#define R_WR 24
#define R_NBLK 32                   // 32 x 32 = 1024 chunks

// ---------------- projection config (persistent, cp.async pipelined) -------
#define PP_NBLK 444                 // 3 blocks/SM x 148 SMs
#define ROWB 528                    // 33 floats * 4B per batch row (pad-33)
#define TILEB (NB * ROWB)           // 135168? no: 256*528 = 135168/2... per tile bytes
// NOTE: TILEB = 256*528 = 135168 B is the padded smem footprint of one tile?
// Actually one tile = 256 rows * 528 B = 135168 B is wrong; 256*528 = 135168.
// We use 2 buffers -> see P_SMEM below. (528*256 = 135,168? 528*256=135168; /2
// buffers would exceed smem. Recheck: 528*256 = 135168 bytes... too big!)
// CORRECT: 528 bytes/row * 256 rows = 135,168?  528*256 = 135,168. That's 132KB!
// -> use 128 batch rows per tile, two tiles cover one t. See below.
#undef TILEB

// One tile = one t x 128 batch rows (half the batches): 128*528 = 67584/2?
// 128 * 528 = 67,584 B. Two buffers = 135,168 B > 228KB/3. Still too big.
// Final layout: tile = one t x 256 rows of 132B?  No.
// Use UNPADDED 128B rows + XOR swizzle for conflict-free LDS instead of pad:
//   row b at offset b*128, compute reads float4 at (b*128 + (q^ (b&7))*16)
//   swizzle makes quarter-warp lanes hit distinct banks.
#define TROWB 128                   // 32 floats, unpadded
#define TILEB (NB * TROWB)          // 32768 B per tile
#define P_SMEM (2 * TILEB)          // 65536 B (double buffer) -> 3 blocks/SM

// ---------------- z-recursion + covs-broadcast config ----------------
#define Z_L 32
#define Z_W 48
#define Z_NCHUNK (TT / Z_L)         // 256
#define Z_MAXSTEPS (Z_L + Z_W)      // 80
#define BC_TILE 32
#define BC_NBLK (TT / BC_TILE)      // 256
#define ZB_SMEM (Z_MAXSTEPS * 26 * 4 + NB * 41 * 4)   // 50304 B

// output offsets (tuple flattened: states, covs, ll)
#define OUT_STATES 0
#define OUT_COVS   ((size_t)NB * TT * SD)
#define OUT_LL     (OUT_COVS + (size_t)NB * TT * SD * SD)

// ============================================================================
// Kernel 1: data-independent Riccati recursion -> g_J, g_U  (standalone!)
// ============================================================================
__global__ __launch_bounds__(32) void k_ricc(
    const float* __restrict__ Ain,
    const float* __restrict__ Cin,
    const float* __restrict__ Qlog,
    const float* __restrict__ Rlog)
{
    const int chunk = blockIdx.x * 32 + threadIdx.x;

    float a[25];
    #pragma unroll
    for (int i = 0; i < 25; i++) a[i] = Ain[i];
    float q[5];
    #pragma unroll
    for (int k = 0; k < 5; k++) q[k] = expf(Qlog[k]);

    float U[25];
    #pragma unroll
    for (int i = 0; i < 25; i++) U[i] = 0.f;
    float logdetR = 0.f;
    for (int o = 0; o < OD; o++) {
        float rl = Rlog[o];
        logdetR += rl;
        float ri = expf(-rl);
        float cv[5];
        #pragma unroll
        for (int k = 0; k < 5; k++) cv[k] = Cin[o * 5 + k];
        #pragma unroll
        for (int i = 0; i < 5; i++) {
            float f = ri * cv[i];
            #pragma unroll
            for (int j = 0; j < 5; j++) U[i * 5 + j] += f * cv[j];
        }
    }
    if (chunk == 0) {
        #pragma unroll
        for (int i = 0; i < 25; i++) g_U[i] = U[i];
    }

    const int town = chunk * R_LR;
    const int tend = town + R_LR;
    int t0s = town - R_WR; if (t0s < 0) t0s = 0;

    float P[25];
    #pragma unroll
    for (int i = 0; i < 25; i++) P[i] = (i % 6 == 0) ? 1.f : 0.f;

    for (int t = t0s; t < tend; ++t) {
        float Tm[25], Pp[25];
        #pragma unroll
        for (int i = 0; i < 5; i++)
            #pragma unroll
            for (int j = 0; j < 5; j++) {
                float s = 0.f;
                #pragma unroll
                for (int k = 0; k < 5; k++) s += a[i * 5 + k] * P[k * 5 + j];
                Tm[i * 5 + j] = s;
            }
        #pragma unroll
        for (int i = 0; i < 5; i++)
            #pragma unroll
            for (int j = 0; j < 5; j++) {
                float s = 0.f;
                #pragma unroll
                for (int k = 0; k < 5; k++) s += Tm[i * 5 + k] * a[j * 5 + k];
                Pp[i * 5 + j] = s;
            }
        #pragma unroll
        for (int i = 0; i < 5; i++) Pp[i * 5 + i] += q[i];

        float M[25], V[25];
        #pragma unroll
        for (int i = 0; i < 5; i++)
            #pragma unroll
            for (int j = 0; j < 5; j++) {
                float s = (i == j) ? 1.f : 0.f;
                #pragma unroll
                for (int k = 0; k < 5; k++) s += U[i * 5 + k] * Pp[k * 5 + j];
                M[i * 5 + j] = s;
            }
        #pragma unroll
        for (int i = 0; i < 25; i++) V[i] = (i % 6 == 0) ? 1.f : 0.f;
        float det = 1.f;
        #pragma unroll
        for (int k = 0; k < 5; k++) {
            float piv = M[k * 5 + k];
            det *= piv;
            float ip = 1.f / piv;
            #pragma unroll
            for (int j = 0; j < 5; j++) { M[k * 5 + j] *= ip; V[k * 5 + j] *= ip; }
            #pragma unroll
            for (int i2 = 0; i2 < 5; i2++) {
                if (i2 == k) continue;
                float f = M[i2 * 5 + k];
                #pragma unroll
                for (int j = 0; j < 5; j++) {
                    M[i2 * 5 + j] -= f * M[k * 5 + j];
                    V[i2 * 5 + j] -= f * V[k * 5 + j];
                }
            }
        }
        #pragma unroll
        for (int i = 0; i < 5; i++)
            #pragma unroll
            for (int j = 0; j < 5; j++) {
                float s = 0.f;
                #pragma unroll
                for (int k = 0; k < 5; k++) s += Pp[i * 5 + k] * V[k * 5 + j];
                P[i * 5 + j] = s;
            }

        if (t >= town) {
            float ld = logdetR + logf(det);
            #pragma unroll
            for (int e = 0; e < 25; e++) g_J[t * 26 + e] = P[e];
            g_J[t * 26 + 25] = ld;
        }
    }
}

// ---------------- cp.async helpers ----------------
__device__ __forceinline__ void cp16(uint32_t saddr, const void* gaddr) {
    asm volatile("cp.async.cg.shared.global [%0], [%1], 16;"
                 :: "r"(saddr), "l"(gaddr));
}
#define CP_COMMIT() asm volatile("cp.async.commit_group;" ::: "memory")
#define CP_WAIT1()  asm volatile("cp.async.wait_group 1;" ::: "memory")

// XOR swizzle: 16B chunk q of row b goes to chunk q ^ (b & 7)
__device__ __forceinline__ uint32_t sw_off(int b, int q) {
    return (uint32_t)(b * TROWB + ((q ^ (b & 7)) << 4));
}

// ============================================================================
// Kernel 2: observation projection y -> g_proj
// Persistent: 444 blocks x 256 thr, each grid-strides over t tiles.
// Double-buffered cp.async (tile = one t x 256 batch rows = 32KB),
// XOR-swizzled rows for conflict-free float4 LDS in compute.
// ============================================================================
__global__ __launch_bounds__(256) void k_proj(
    const float* __restrict__ y,
    const float* __restrict__ Cin,
    const float* __restrict__ Rlog)
{
    extern __shared__ float sy[];            // [2][NB][32] swizzled
    __shared__ float pp[OD * 8];             // {crv0..4, rin, 0, 0} per o
    const int tid = threadIdx.x;

    if (tid < OD) {
        float ri = expf(-Rlog[tid]);
        #pragma unroll
        for (int k = 0; k < 5; k++) pp[tid * 8 + k] = Cin[tid * 5 + k] * ri;
        pp[tid * 8 + 5] = ri;
        pp[tid * 8 + 6] = 0.f;
        pp[tid * 8 + 7] = 0.f;
    }
    __syncthreads();

    const uint32_t sbase =
        (uint32_t)__cvta_generic_to_shared(sy);
    const char* yb = (const char*)y;

    // per-thread load slice: 8 chunks; f = it*256+tid -> b = f>>3, q = f&7
    int t = blockIdx.x;
    int buf = 0;

    // prologue: load tile t into buf 0
    {
        #pragma unroll
        for (int it = 0; it < 8; ++it) {
            int f = it * 256 + tid;
            int b = f >> 3, q = f & 7;
            cp16(sbase + sw_off(b, q),
                 yb + ((size_t)b * TT + t) * 128 + q * 16);
        }
        CP_COMMIT();
    }

    while (t < TT) {
        const int tn = t + PP_NBLK;
        // issue next tile into the other buffer
        if (tn < TT) {
            #pragma unroll
            for (int it = 0; it < 8; ++it) {
                int f = it * 256 + tid;
                int b = f >> 3, q = f & 7;
                cp16(sbase + (1 - buf) * TILEB + sw_off(b, q),
                     yb + ((size_t)b * TT + tn) * 128 + q * 16);
            }
        }
        CP_COMMIT();
        CP_WAIT1();            // current buffer's group complete
        __syncthreads();

        // compute: thread = batch row b
        const int b = tid;
        const float* base = sy + (buf * TILEB) / 4;
        float v[OD];
        #pragma unroll
        for (int q = 0; q < 8; q++) {
            const float4 x = *(const float4*)((const char*)base + sw_off(b, q));
            v[q * 4 + 0] = x.x; v[q * 4 + 1] = x.y;
            v[q * 4 + 2] = x.z; v[q * 4 + 3] = x.w;
        }
        float c0 = 0, c1 = 0, c2 = 0, c3 = 0, c4 = 0, syy = 0;
        const float4* p4 = (const float4*)pp;
        #pragma unroll
        for (int o = 0; o < OD; o++) {
            float4 pa = p4[o * 2];
            float4 pb = p4[o * 2 + 1];
            float yv = v[o];
            c0 += pa.x * yv;
            c1 += pa.y * yv;
            c2 += pa.z * yv;
            c3 += pa.w * yv;
            c4 += pb.x * yv;
            syy += (pb.y * yv) * yv;
        }
        float* pd = &g_proj[((size_t)t * 6) * NB + b];
        pd[0 * NB] = c0; pd[1 * NB] = c1; pd[2 * NB] = c2;
        pd[3 * NB] = c3; pd[4 * NB] = c4; pd[5 * NB] = syy;

        __syncthreads();       // all reads of this buffer done before reuse
        buf ^= 1;
        t = tn;
    }
}

// ---------------- one z step ----------------
#define Z_STEP(CCBUF, U_)                                                     \
    {                                                                         \
        float zp[5];                                                          \
        _Pragma("unroll")                                                     \
        for (int i = 0; i < 5; i++)                                           \
            zp[i] = a[i*5+0]*z0 + a[i*5+1]*z1 + a[i*5+2]*z2                   \
                  + a[i*5+3]*z3 + a[i*5+4]*z4;                                \
        float g[5];                                                           \
        _Pragma("unroll")                                                     \
        for (int i = 0; i < 5; i++) {                                         \
            float sa = 0.f;                                                   \
            _Pragma("unroll")                                                 \
            for (int j = 0; j < 5; j++) sa += U_[i*5+j] * zp[j];              \
            g[i] = sa;                                                        \
        }                                                                     \
        float w[5];                                                           \
        _Pragma("unroll")                                                     \
        for (int i = 0; i < 5; i++) w[i] = (CCBUF)[i] - g[i];                 \
        const float* Jr = &sJ[s * 26];                                        \
        float h[5];                                                           \
        _Pragma("unroll")                                                     \
        for (int i = 0; i < 5; i++) {                                         \
            float sa = 0.f;                                                   \
            _Pragma("unroll")                                                 \
            for (int j = 0; j < 5; j++) sa += Jr[i*5+j] * w[j];               \
            h[i] = sa;                                                        \
        }                                                                     \
        z0 = zp[0]+h[0]; z1 = zp[1]+h[1]; z2 = zp[2]+h[2];                    \
        z3 = zp[3]+h[3]; z4 = zp[4]+h[4];                                     \
        if (s >= warm) {                                                      \
            float cz = 0, zg = 0, wh = 0;                                     \
            _Pragma("unroll")                                                 \
            for (int i = 0; i < 5; i++) {                                     \
                cz += (CCBUF)[i]*zp[i]; zg += zp[i]*g[i]; wh += w[i]*h[i];    \
            }                                                                 \
            float quad = (CCBUF)[5] - 2.f*cz + zg - wh;                       \
            ll -= 0.5f * ((float)OD * 1.8378770664093453f                     \
                          + Jr[25] + quad);                                   \
            int sl = (s - warm) & 7;                                          \
            float* sb = &sbuf[b * 41 + sl * 5];                               \
            sb[0]=z0; sb[1]=z1; sb[2]=z2; sb[3]=z3; sb[4]=z4;                 \
        }                                                                     \
    }

// ============================================================================
// Kernel 3: fused  (a) z-recursion + states + ll partials [blocks 0..255]
//                  (b) covariance broadcast J -> covs     [blocks 256..511]
// BC's 210MB streaming write fills HBM while z-blocks sit on serial chains.
// ============================================================================
__global__ __launch_bounds__(256) void k_zbc(
    const float* __restrict__ Ain, float* __restrict__ out)
{
    extern __shared__ float sm[];
    const int tid = threadIdx.x;

    if (blockIdx.x < Z_NCHUNK) {
        float* sJ   = sm;                         // [Z_MAXSTEPS][26]
        float* sbuf = sm + Z_MAXSTEPS * 26;       // [NB][41]

        const int chunk = blockIdx.x;
        const int town = chunk * Z_L;
        int t0 = town - Z_W; if (t0 < 0) t0 = 0;
        const int nsteps = town + Z_L - t0;       // 32 or 80 (both %8==0)
        const int warm = town - t0;               // 0 or 48

        for (int i = tid; i < nsteps * 26; i += 256) sJ[i] = g_J[t0 * 26 + i];
        __syncthreads();

        float a[25], U[25];
        #pragma unroll
        for (int i = 0; i < 25; i++) { a[i] = Ain[i]; U[i] = g_U[i]; }

        float z0 = 0, z1 = 0, z2 = 0, z3 = 0, z4 = 0;
        float ll = 0.f;
        const int b = tid;
        const float* pbase = &g_proj[(size_t)t0 * 6 * NB + b];

        float bufA[4][6], bufB[4][6];
        #pragma unroll
        for (int u = 0; u < 4; u++)
            #pragma unroll
            for (int k = 0; k < 6; k++)
                bufA[u][k] = pbase[((size_t)u * 6 + k) * NB];

        for (int s8 = 0; s8 < nsteps; s8 += 8) {
            if (s8 + 4 < nsteps) {
                const float* pn = pbase + (size_t)(s8 + 4) * 6 * NB;
                #pragma unroll
                for (int u = 0; u < 4; u++)
                    #pragma unroll
                    for (int k = 0; k < 6; k++)
                        bufB[u][k] = pn[((size_t)u * 6 + k) * NB];
            }
            #pragma unroll
            for (int u = 0; u < 4; u++) {
                const int s = s8 + u;
                Z_STEP(bufA[u], U)
            }
            if (s8 + 8 < nsteps) {
                const float* pn = pbase + (size_t)(s8 + 8) * 6 * NB;
                #pragma unroll
                for (int u = 0; u < 4; u++)
                    #pragma unroll
                    for (int k = 0; k < 6; k++)
                        bufA[u][k] = pn[((size_t)u * 6 + k) * NB];
            }
            #pragma unroll
            for (int u = 0; u < 4; u++) {
                const int s = s8 + 4 + u;
                Z_STEP(bufB[u], U)
            }
            if (s8 >= warm) {
                __syncthreads();
                const int tflush0 = town + (s8 - warm);
                for (int f = tid; f < NB * 40; f += 256) {
                    int bb = f / 40;
                    int u  = f % 40;
                    __stcs(&out[OUT_STATES + ((size_t)bb * TT + tflush0) * 5 + u],
                           sbuf[bb * 41 + u]);
                }
                __syncthreads();
            }
        }
        g_llpart[(size_t)b * Z_NCHUNK + chunk] = ll;
    } else {
        // ---- covariance broadcast: contiguous float4 streaming stores ----
        const int v = blockIdx.x - Z_NCHUNK;       // 0..255
        const int t0 = v * BC_TILE;
        float* sJ = sm;                            // 800 floats
        for (int i = tid; i < BC_TILE * 25; i += 256) {
            int tt = i / 25;
            int e  = i % 25;
            sJ[i] = g_J[(t0 + tt) * 26 + e];
        }
        __syncthreads();
        const float4* sJ4 = (const float4*)sJ;     // 200 float4
        float4* out4 = (float4*)(out + OUT_COVS);
        const unsigned base = (unsigned)v * 200u;
        if (tid < 200) {
            float4 val = sJ4[tid];
            #pragma unroll 4
            for (int bb = 0; bb < NB; ++bb) {
                __stcs(&out4[(size_t)bb * (TT * 25 / 4) + base + tid], val);
            }
        }
    }
}

// ============================================================================
// Kernel 4: ll reduction — block = one batch, 32 lanes, butterfly reduce
// ============================================================================
__global__ __launch_bounds__(32) void k_ll(float* __restrict__ out)
{
    const int b = blockIdx.x;
    const int lane = threadIdx.x;
    const float* p = &g_llpart[(size_t)b * Z_NCHUNK];
    float s = 0.f;
    #pragma unroll
    for (int k = 0; k < Z_NCHUNK / 32; k++) s += p[lane + k * 32];
    #pragma unroll
    for (int d = 16; d >= 1; d >>= 1)
        s += __shfl_xor_sync(0xFFFFFFFFu, s, d);
    if (lane == 0) out[OUT_LL + b] = s;
}

// ============================================================================
extern "C" void kernel_launch(void* const* d_in, const int* in_sizes, int n_in,
                              void* d_out, int out_size)
{
    const float* y  = (const float*)d_in[0];
    const float* A  = (const float*)d_in[1];
    const float* C  = (const float*)d_in[2];
    const float* Ql = (const float*)d_in[3];
    const float* Rl = (const float*)d_in[4];
    float* out = (float*)d_out;

    cudaFuncSetAttribute(k_proj, cudaFuncAttributeMaxDynamicSharedMemorySize, P_SMEM);
    cudaFuncSetAttribute(k_zbc, cudaFuncAttributeMaxDynamicSharedMemorySize, ZB_SMEM);

    k_ricc<<<R_NBLK, 32>>>(A, C, Ql, Rl);
    k_proj<<<PP_NBLK, 256, P_SMEM>>>(y, C, Rl);
    k_zbc<<<Z_NCHUNK + BC_NBLK, 256, ZB_SMEM>>>(A, out);
    k_ll<<<NB, 32>>>(out);
}